// round 12
// baseline (speedup 1.0000x reference)
#include <cuda_runtime.h>
#include <cuda_bf16.h>
#include <cstdint>

#define CH 32
#define KNB 27
#define TM 128
#define SM_WB 49152
#define SM_IDX 61440
#define SM_TOT 75264

__device__ __align__(128) uint32_t g_xp [(size_t)2000128 * 32];
__device__ __align__(128) uint32_t g_h1p[(size_t)2000128 * 32];
__device__ __align__(128) float    g_h1 [(size_t)2000128 * 32];
__device__ __align__(128) uint32_t g_w1img[KNB * 1024];
__device__ __align__(128) uint32_t g_w2img[KNB * 1024];
__device__ float g_part[15700 * 64];
__device__ float g_bn[64];

__device__ __forceinline__ void cpa16s(uint32_t d, const void* s) {
    asm volatile("cp.async.cg.shared.global [%0], [%1], 16;" :: "r"(d), "l"(s));
}
__device__ __forceinline__ void ldm4(uint32_t* r, uint32_t a) {
    asm volatile("ldmatrix.sync.aligned.m8n8.x4.shared.b16 {%0,%1,%2,%3}, [%4];"
                 : "=r"(r[0]), "=r"(r[1]), "=r"(r[2]), "=r"(r[3]) : "r"(a));
}
__device__ __forceinline__ void hmma(float* d, const uint32_t* a, const uint32_t* b) {
    asm volatile("mma.sync.aligned.m16n8k16.row.col.f32.bf16.bf16.f32 "
                 "{%0,%1,%2,%3}, {%4,%5,%6,%7}, {%8,%9}, {%0,%1,%2,%3};"
                 : "+f"(d[0]), "+f"(d[1]), "+f"(d[2]), "+f"(d[3])
                 : "r"(a[0]), "r"(a[1]), "r"(a[2]), "r"(a[3]), "r"(b[0]), "r"(b[1]));
}
__device__ __forceinline__ unsigned short bf16u(float v) {
    return __bfloat16_as_ushort(__float2bfloat16(v));
}

// Gathered GEMM via mma.sync bf16 hi/lo split, 3-stage cp.async pipeline,
// fused BN stats. A rows (128B = [hi|lo]) XOR-16B-chunk swizzled.
__global__ void __launch_bounds__(128, 3)
conv_mma(const uint32_t* __restrict__ xp, const int* __restrict__ nbr,
         const uint32_t* __restrict__ wimg, float* __restrict__ outp, int n)
{
    extern __shared__ __align__(1024) char smraw[];
    const uint32_t sb = (uint32_t)__cvta_generic_to_shared(smraw);
    int* idxs = (int*)(smraw + SM_IDX);
    const int t = threadIdx.x, w = t >> 5, l = t & 31, base = blockIdx.x * TM;

    for (int i = t; i < KNB * TM; i += 128) {
        int r = i / KNB, k = i - r * KNB;
        idxs[k * TM + r] = (base + r < n) ? nbr[(size_t)base * KNB + i] : 0;
    }
    __syncthreads();

    // stage gather: buf s <- offset k
    auto gather = [&](int s, int k) {
        const uint32_t ab = sb + s * 16384;
        const uint32_t wb = sb + SM_WB + s * 4096;
        const uint32_t* src = xp + (size_t)idxs[k * TM + t] * 32;
        #pragma unroll
        for (int q = 0; q < 8; q++)
            cpa16s(ab + t * 128 + ((q ^ (t & 7)) << 4), src + q * 4);
        const uint32_t* ws = wimg + k * 1024 + t * 8;
        cpa16s(wb + t * 32, ws);
        cpa16s(wb + t * 32 + 16, ws + 4);
        asm volatile("cp.async.commit_group;" ::: "memory");
    };

    gather(0, 0);
    gather(1, 1);

    float df[2][4][4];
    #pragma unroll
    for (int mt = 0; mt < 2; mt++)
        #pragma unroll
        for (int nt = 0; nt < 4; nt++)
            #pragma unroll
            for (int e = 0; e < 4; e++) df[mt][nt][e] = 0.f;

    #pragma unroll 1
    for (int k = 0; k < KNB; k++) {
        if (k + 1 < KNB) asm volatile("cp.async.wait_group 1;" ::: "memory");
        else             asm volatile("cp.async.wait_group 0;" ::: "memory");
        __syncthreads();                       // stage-k visible; iter k-1 compute done
        if (k + 2 < KNB) gather((k + 2) % 3, k + 2);

        const uint32_t ab = sb + (k % 3) * 16384;
        uint32_t af[2][2][2][4];               // [img][mt][kt][4]
        #pragma unroll
        for (int img = 0; img < 2; img++)
            #pragma unroll
            for (int mt = 0; mt < 2; mt++)
                #pragma unroll
                for (int kt = 0; kt < 2; kt++) {
                    int row = w * 32 + mt * 16 + (l & 15);
                    int ch  = img * 4 + kt * 2 + (l >> 4);
                    ldm4(af[img][mt][kt], ab + row * 128 + ((ch ^ (row & 7)) << 4));
                }

        const uint4* wq = (const uint4*)(smraw + SM_WB + (k % 3) * 4096);
        uint32_t bh[2][4][2], bl[2][4][2];     // [kt][nt][2]
        #pragma unroll
        for (int j = 0; j < 4; j++) {
            uint4 v = wq[j * 32 + l];
            int f0 = 2 * j, f1 = 2 * j + 1;
            bh[(f0 >> 2) & 1][f0 & 3][0] = v.x;  bh[(f0 >> 2) & 1][f0 & 3][1] = v.y;
            bh[(f1 >> 2) & 1][f1 & 3][0] = v.z;  bh[(f1 >> 2) & 1][f1 & 3][1] = v.w;
        }
        #pragma unroll
        for (int j = 4; j < 8; j++) {
            uint4 v = wq[j * 32 + l];
            int f0 = 2 * j - 8, f1 = 2 * j - 7;
            bl[(f0 >> 2) & 1][f0 & 3][0] = v.x;  bl[(f0 >> 2) & 1][f0 & 3][1] = v.y;
            bl[(f1 >> 2) & 1][f1 & 3][0] = v.z;  bl[(f1 >> 2) & 1][f1 & 3][1] = v.w;
        }

        #pragma unroll
        for (int mt = 0; mt < 2; mt++)
            #pragma unroll
            for (int nt = 0; nt < 4; nt++)
                #pragma unroll
                for (int kt = 0; kt < 2; kt++) {
                    hmma(df[mt][nt], af[0][mt][kt], bh[kt][nt]);   // hi*Wh
                    hmma(df[mt][nt], af[1][mt][kt], bh[kt][nt]);   // lo*Wh
                    hmma(df[mt][nt], af[0][mt][kt], bl[kt][nt]);   // hi*Wl
                }
    }

    const int g2 = l >> 2, tc = (l & 3) * 2;
    #pragma unroll
    for (int mt = 0; mt < 2; mt++)
        #pragma unroll
        for (int nt = 0; nt < 4; nt++) {
            int r0 = base + w * 32 + mt * 16 + g2;
            int c  = nt * 8 + tc;
            if (r0 < n)
                *(float2*)(outp + (size_t)r0 * CH + c) = make_float2(df[mt][nt][0], df[mt][nt][1]);
            if (r0 + 8 < n)
                *(float2*)(outp + (size_t)(r0 + 8) * CH + c) = make_float2(df[mt][nt][2], df[mt][nt][3]);
        }

    // fused BN stats (deterministic)
    __syncthreads();
    float* ssum = (float*)smraw;               // 128*33
    float* ssq  = (float*)(smraw + 16896);
    #pragma unroll
    for (int mt = 0; mt < 2; mt++)
        #pragma unroll
        for (int nt = 0; nt < 4; nt++) {
            int rl = w * 32 + mt * 16 + g2;
            int c  = nt * 8 + tc;
            bool v0 = (base + rl) < n, v1 = (base + rl + 8) < n;
            float a = v0 ? df[mt][nt][0] : 0.f, b = v0 ? df[mt][nt][1] : 0.f;
            float cc = v1 ? df[mt][nt][2] : 0.f, dd = v1 ? df[mt][nt][3] : 0.f;
            ssum[rl * 33 + c] = a;        ssum[rl * 33 + c + 1] = b;
            ssum[(rl + 8) * 33 + c] = cc; ssum[(rl + 8) * 33 + c + 1] = dd;
            ssq[rl * 33 + c] = a * a;        ssq[rl * 33 + c + 1] = b * b;
            ssq[(rl + 8) * 33 + c] = cc * cc; ssq[(rl + 8) * 33 + c + 1] = dd * dd;
        }
    __syncthreads();
    if (t < 32) {
        float s = 0.f, q2 = 0.f;
        for (int i = 0; i < TM; i++) { s += ssum[i * 33 + t]; q2 += ssq[i * 33 + t]; }
        g_part[(size_t)blockIdx.x * 64 + t]      = s;
        g_part[(size_t)blockIdx.x * 64 + 32 + t] = q2;
    }
}

// Pack W[k][ci][co] fp32 -> per-k B-fragment-ordered bf16 hi/lo image.
__global__ void wprep(const float* __restrict__ W, uint32_t* __restrict__ img)
{
    int i = blockIdx.x * blockDim.x + threadIdx.x;
    if (i >= KNB * 1024) return;
    int k = i >> 10, rem = i & 1023;
    int j = rem >> 7, lr = rem & 127, lane = lr >> 2, s = lr & 3;
    int f = 2 * j + (s >> 1), r = s & 1;
    int im = f >> 3, kt = (f >> 2) & 1, nt = f & 3;
    int ci0 = kt * 16 + r * 8 + (lane & 3) * 2;
    int co  = nt * 8 + (lane >> 2);
    float v0 = W[k * 1024 + ci0 * 32 + co];
    float v1 = W[k * 1024 + (ci0 + 1) * 32 + co];
    unsigned short p0, p1;
    if (im == 0) { p0 = bf16u(v0); p1 = bf16u(v1); }
    else {
        p0 = bf16u(v0 - __bfloat162float(__ushort_as_bfloat16(bf16u(v0))));
        p1 = bf16u(v1 - __bfloat162float(__ushort_as_bfloat16(bf16u(v1))));
    }
    img[i] = (uint32_t)p0 | ((uint32_t)p1 << 16);
}

__global__ void xprep(const float* __restrict__ x, uint32_t* __restrict__ xp, int n)
{
    int j = blockIdx.x * blockDim.x + threadIdx.x;
    int total = n * 16, stride = gridDim.x * blockDim.x;
    for (int i = j; i < total; i += stride) {
        int row = i >> 4, wp = i & 15;
        float2 v = *(const float2*)(x + (size_t)row * 32 + wp * 2);
        unsigned short h0 = bf16u(v.x), h1 = bf16u(v.y);
        float l0 = v.x - __bfloat162float(__ushort_as_bfloat16(h0));
        float l1 = v.y - __bfloat162float(__ushort_as_bfloat16(h1));
        xp[(size_t)row * 32 + wp]      = (uint32_t)h0 | ((uint32_t)h1 << 16);
        xp[(size_t)row * 32 + 16 + wp] = (uint32_t)bf16u(l0) | ((uint32_t)bf16u(l1) << 16);
    }
}

__global__ void bnreluprep(const float* __restrict__ x, uint32_t* __restrict__ xp, int n)
{
    int j = blockIdx.x * blockDim.x + threadIdx.x;
    int total = n * 16, stride = gridDim.x * blockDim.x;
    int wp0 = j & 15;
    float sc0 = g_bn[2 * wp0], sc1 = g_bn[2 * wp0 + 1];
    float sh0 = g_bn[32 + 2 * wp0], sh1 = g_bn[33 + 2 * wp0];
    for (int i = j; i < total; i += stride) {
        int row = i >> 4, wp = i & 15;
        float2 v = *(const float2*)(x + (size_t)row * 32 + wp * 2);
        float a = fmaxf(v.x * sc0 + sh0, 0.f);
        float b = fmaxf(v.y * sc1 + sh1, 0.f);
        unsigned short h0 = bf16u(a), h1 = bf16u(b);
        float l0 = a - __bfloat162float(__ushort_as_bfloat16(h0));
        float l1 = b - __bfloat162float(__ushort_as_bfloat16(h1));
        xp[(size_t)row * 32 + wp]      = (uint32_t)h0 | ((uint32_t)h1 << 16);
        xp[(size_t)row * 32 + 16 + wp] = (uint32_t)bf16u(l0) | ((uint32_t)bf16u(l1) << 16);
    }
}

__global__ void reduce_kernel(const float* __restrict__ gamma,
                              const float* __restrict__ beta, int n, int nblk)
{
    __shared__ double sd[512];
    __shared__ double comb[64];
    const int t = threadIdx.x;
    const int c = t & 63, s = t >> 6;
    double acc = 0.0;
    for (int i = s; i < nblk; i += 8) acc += (double)g_part[(size_t)i * 64 + c];
    sd[t] = acc;
    __syncthreads();
    if (t < 64) {
        double a = 0.0;
        #pragma unroll
        for (int s2 = 0; s2 < 8; s2++) a += sd[t + 64 * s2];
        comb[t] = a;
    }
    __syncthreads();
    if (t < 32) {
        double mean = comb[t] / (double)n;
        double var  = comb[32 + t] / (double)n - mean * mean;
        float sc = (float)((double)gamma[t] / sqrt(var + 1e-4));
        float sh = (float)((double)beta[t] - mean * (double)sc);
        g_bn[t] = sc; g_bn[32 + t] = sh;
    }
}

__global__ void final_kernel(float* __restrict__ out, const float* __restrict__ feat, int n)
{
    int j = blockIdx.x * blockDim.x + threadIdx.x;
    int total = n * 8, stride = gridDim.x * blockDim.x;
    int m = j & 7;
    float4 sc = *(const float4*)(g_bn + m * 4);
    float4 sh = *(const float4*)(g_bn + 32 + m * 4);
    float4* o4 = (float4*)out;
    const float4* f4 = (const float4*)feat;
    for (int i = j; i < total; i += stride) {
        float4 v = o4[i], f = f4[i];
        v.x = fmaxf(v.x * sc.x + sh.x + f.x, 0.f);
        v.y = fmaxf(v.y * sc.y + sh.y + f.y, 0.f);
        v.z = fmaxf(v.z * sc.z + sh.z + f.z, 0.f);
        v.w = fmaxf(v.w * sc.w + sh.w + f.w, 0.f);
        o4[i] = v;
    }
}

extern "C" void kernel_launch(void* const* d_in, const int* in_sizes, int n_in,
                              void* d_out, int out_size)
{
    const float* feat = (const float*)d_in[0];
    const int*   nbr  = (const int*)  d_in[1];
    const float* W1   = (const float*)d_in[2];
    const float* g1   = (const float*)d_in[3];
    const float* b1   = (const float*)d_in[4];
    const float* W2   = (const float*)d_in[5];
    const float* g2   = (const float*)d_in[6];
    const float* b2   = (const float*)d_in[7];
    int n = in_sizes[0] / CH;
    float* out = (float*)d_out;

    float *h1, *xpf, *h1pf;
    uint32_t *w1i, *w2i;
    cudaGetSymbolAddress((void**)&h1,   g_h1);
    cudaGetSymbolAddress((void**)&xpf,  g_xp);
    cudaGetSymbolAddress((void**)&h1pf, g_h1p);
    cudaGetSymbolAddress((void**)&w1i,  g_w1img);
    cudaGetSymbolAddress((void**)&w2i,  g_w2img);

    cudaFuncSetAttribute(conv_mma, cudaFuncAttributeMaxDynamicSharedMemorySize, SM_TOT);
    int grid = (n + TM - 1) / TM;

    wprep<<<(KNB * 1024 + 255) / 256, 256>>>(W1, w1i);
    wprep<<<(KNB * 1024 + 255) / 256, 256>>>(W2, w2i);
    xprep<<<2048, 256>>>(feat, (uint32_t*)xpf, n);
    conv_mma<<<grid, 128, SM_TOT>>>((const uint32_t*)xpf, nbr, w1i, h1, n);
    reduce_kernel<<<1, 512>>>(g1, b1, n, grid);
    bnreluprep<<<2048, 256>>>(h1, (uint32_t*)h1pf, n);
    conv_mma<<<grid, 128, SM_TOT>>>((const uint32_t*)h1pf, nbr, w2i, out, n);
    reduce_kernel<<<1, 512>>>(g2, b2, n, grid);
    final_kernel<<<2048, 256>>>(out, feat, n);
}

// round 13
// speedup vs baseline: 1.6696x; 1.6696x over previous
#include <cuda_runtime.h>
#include <cuda_bf16.h>
#include <cstdint>

#define CH 32
#define KNB 27
#define TM 128
#define SM_WB 49152
#define SM_IDX 61440
#define SM_TOT 75264

__device__ __align__(128) uint32_t g_xp [(size_t)2000128 * 32];
__device__ __align__(128) uint32_t g_h1p[(size_t)2000128 * 32];
__device__ __align__(128) float    g_h1 [(size_t)2000128 * 32];
__device__ __align__(128) uint32_t g_w1img[KNB * 1024];
__device__ __align__(128) uint32_t g_w2img[KNB * 1024];
__device__ float g_part[15700 * 64];
__device__ float g_bn[64];

__device__ __forceinline__ void cpa16s(uint32_t d, const void* s) {
    asm volatile("cp.async.cg.shared.global [%0], [%1], 16;" :: "r"(d), "l"(s));
}
__device__ __forceinline__ void ldm4(uint32_t* r, uint32_t a) {
    asm volatile("ldmatrix.sync.aligned.m8n8.x4.shared.b16 {%0,%1,%2,%3}, [%4];"
                 : "=r"(r[0]), "=r"(r[1]), "=r"(r[2]), "=r"(r[3]) : "r"(a));
}
__device__ __forceinline__ void hmma(float* d, const uint32_t* a, const uint32_t* b) {
    asm volatile("mma.sync.aligned.m16n8k16.row.col.f32.bf16.bf16.f32 "
                 "{%0,%1,%2,%3}, {%4,%5,%6,%7}, {%8,%9}, {%0,%1,%2,%3};"
                 : "+f"(d[0]), "+f"(d[1]), "+f"(d[2]), "+f"(d[3])
                 : "r"(a[0]), "r"(a[1]), "r"(a[2]), "r"(a[3]), "r"(b[0]), "r"(b[1]));
}
__device__ __forceinline__ unsigned short bf16u(float v) {
    return __bfloat16_as_ushort(__float2bfloat16(v));
}

// Gathered GEMM via mma.sync bf16 hi/lo split, 3-stage cp.async pipeline,
// fused BN stats. Gather is COOPERATIVE: 8 consecutive lanes load the 8x16B
// chunks of one 128B row -> 4 full lines per warp-instruction (coalesced).
__global__ void __launch_bounds__(128, 3)
conv_mma(const uint32_t* __restrict__ xp, const int* __restrict__ nbr,
         const uint32_t* __restrict__ wimg, float* __restrict__ outp, int n)
{
    extern __shared__ __align__(1024) char smraw[];
    const uint32_t sb = (uint32_t)__cvta_generic_to_shared(smraw);
    int* idxs = (int*)(smraw + SM_IDX);
    const int t = threadIdx.x, w = t >> 5, l = t & 31, base = blockIdx.x * TM;

    for (int i = t; i < KNB * TM; i += 128) {
        int r = i / KNB, k = i - r * KNB;
        idxs[k * TM + r] = (base + r < n) ? nbr[(size_t)base * KNB + i] : 0;
    }
    __syncthreads();

    const int q  = t & 7;     // chunk within row
    const int rg = t >> 3;    // row group (0..15)

    // stage gather: buf s <- offset k (8 threads cooperate per row)
    auto gather = [&](int s, int k) {
        const uint32_t ab = sb + s * 16384;
        const uint32_t wb = sb + SM_WB + s * 4096;
        const int* id = idxs + k * TM;
        #pragma unroll
        for (int p = 0; p < 8; p++) {
            int r = rg + p * 16;
            cpa16s(ab + r * 128 + ((q ^ (r & 7)) << 4),
                   xp + (size_t)id[r] * 32 + q * 4);
        }
        const uint32_t* ws = wimg + k * 1024 + t * 8;
        cpa16s(wb + t * 32, ws);
        cpa16s(wb + t * 32 + 16, ws + 4);
        asm volatile("cp.async.commit_group;" ::: "memory");
    };

    gather(0, 0);
    gather(1, 1);

    float df[2][4][4];
    #pragma unroll
    for (int mt = 0; mt < 2; mt++)
        #pragma unroll
        for (int nt = 0; nt < 4; nt++)
            #pragma unroll
            for (int e = 0; e < 4; e++) df[mt][nt][e] = 0.f;

    #pragma unroll 1
    for (int k = 0; k < KNB; k++) {
        if (k + 1 < KNB) asm volatile("cp.async.wait_group 1;" ::: "memory");
        else             asm volatile("cp.async.wait_group 0;" ::: "memory");
        __syncthreads();                       // stage-k visible; iter k-1 compute done
        if (k + 2 < KNB) gather((k + 2) % 3, k + 2);

        const uint32_t ab = sb + (k % 3) * 16384;
        uint32_t af[2][2][2][4];               // [img][mt][kt][4]
        #pragma unroll
        for (int img = 0; img < 2; img++)
            #pragma unroll
            for (int mt = 0; mt < 2; mt++)
                #pragma unroll
                for (int kt = 0; kt < 2; kt++) {
                    int row = w * 32 + mt * 16 + (l & 15);
                    int ch  = img * 4 + kt * 2 + (l >> 4);
                    ldm4(af[img][mt][kt], ab + row * 128 + ((ch ^ (row & 7)) << 4));
                }

        const uint4* wq = (const uint4*)(smraw + SM_WB + (k % 3) * 4096);
        uint32_t bh[2][4][2], bl[2][4][2];     // [kt][nt][2]
        #pragma unroll
        for (int j = 0; j < 4; j++) {
            uint4 v = wq[j * 32 + l];
            int f0 = 2 * j, f1 = 2 * j + 1;
            bh[(f0 >> 2) & 1][f0 & 3][0] = v.x;  bh[(f0 >> 2) & 1][f0 & 3][1] = v.y;
            bh[(f1 >> 2) & 1][f1 & 3][0] = v.z;  bh[(f1 >> 2) & 1][f1 & 3][1] = v.w;
        }
        #pragma unroll
        for (int j = 4; j < 8; j++) {
            uint4 v = wq[j * 32 + l];
            int f0 = 2 * j - 8, f1 = 2 * j - 7;
            bl[(f0 >> 2) & 1][f0 & 3][0] = v.x;  bl[(f0 >> 2) & 1][f0 & 3][1] = v.y;
            bl[(f1 >> 2) & 1][f1 & 3][0] = v.z;  bl[(f1 >> 2) & 1][f1 & 3][1] = v.w;
        }

        #pragma unroll
        for (int mt = 0; mt < 2; mt++)
            #pragma unroll
            for (int nt = 0; nt < 4; nt++)
                #pragma unroll
                for (int kt = 0; kt < 2; kt++) {
                    hmma(df[mt][nt], af[0][mt][kt], bh[kt][nt]);   // hi*Wh
                    hmma(df[mt][nt], af[1][mt][kt], bh[kt][nt]);   // lo*Wh
                    hmma(df[mt][nt], af[0][mt][kt], bl[kt][nt]);   // hi*Wl
                }
    }

    const int g2 = l >> 2, tc = (l & 3) * 2;
    #pragma unroll
    for (int mt = 0; mt < 2; mt++)
        #pragma unroll
        for (int nt = 0; nt < 4; nt++) {
            int r0 = base + w * 32 + mt * 16 + g2;
            int c  = nt * 8 + tc;
            if (r0 < n)
                *(float2*)(outp + (size_t)r0 * CH + c) = make_float2(df[mt][nt][0], df[mt][nt][1]);
            if (r0 + 8 < n)
                *(float2*)(outp + (size_t)(r0 + 8) * CH + c) = make_float2(df[mt][nt][2], df[mt][nt][3]);
        }

    // fused BN stats (deterministic)
    __syncthreads();
    float* ssum = (float*)smraw;               // 128*33
    float* ssq  = (float*)(smraw + 16896);
    #pragma unroll
    for (int mt = 0; mt < 2; mt++)
        #pragma unroll
        for (int nt = 0; nt < 4; nt++) {
            int rl = w * 32 + mt * 16 + g2;
            int c  = nt * 8 + tc;
            bool v0 = (base + rl) < n, v1 = (base + rl + 8) < n;
            float a = v0 ? df[mt][nt][0] : 0.f, b = v0 ? df[mt][nt][1] : 0.f;
            float cc = v1 ? df[mt][nt][2] : 0.f, dd = v1 ? df[mt][nt][3] : 0.f;
            ssum[rl * 33 + c] = a;        ssum[rl * 33 + c + 1] = b;
            ssum[(rl + 8) * 33 + c] = cc; ssum[(rl + 8) * 33 + c + 1] = dd;
            ssq[rl * 33 + c] = a * a;        ssq[rl * 33 + c + 1] = b * b;
            ssq[(rl + 8) * 33 + c] = cc * cc; ssq[(rl + 8) * 33 + c + 1] = dd * dd;
        }
    __syncthreads();
    if (t < 32) {
        float s = 0.f, q2 = 0.f;
        for (int i = 0; i < TM; i++) { s += ssum[i * 33 + t]; q2 += ssq[i * 33 + t]; }
        g_part[(size_t)blockIdx.x * 64 + t]      = s;
        g_part[(size_t)blockIdx.x * 64 + 32 + t] = q2;
    }
}

// Pack W[k][ci][co] fp32 -> per-k B-fragment-ordered bf16 hi/lo image.
__global__ void wprep(const float* __restrict__ W, uint32_t* __restrict__ img)
{
    int i = blockIdx.x * blockDim.x + threadIdx.x;
    if (i >= KNB * 1024) return;
    int k = i >> 10, rem = i & 1023;
    int j = rem >> 7, lr = rem & 127, lane = lr >> 2, s = lr & 3;
    int f = 2 * j + (s >> 1), r = s & 1;
    int im = f >> 3, kt = (f >> 2) & 1, nt = f & 3;
    int ci0 = kt * 16 + r * 8 + (lane & 3) * 2;
    int co  = nt * 8 + (lane >> 2);
    float v0 = W[k * 1024 + ci0 * 32 + co];
    float v1 = W[k * 1024 + (ci0 + 1) * 32 + co];
    unsigned short p0, p1;
    if (im == 0) { p0 = bf16u(v0); p1 = bf16u(v1); }
    else {
        p0 = bf16u(v0 - __bfloat162float(__ushort_as_bfloat16(bf16u(v0))));
        p1 = bf16u(v1 - __bfloat162float(__ushort_as_bfloat16(bf16u(v1))));
    }
    img[i] = (uint32_t)p0 | ((uint32_t)p1 << 16);
}

__global__ void xprep(const float* __restrict__ x, uint32_t* __restrict__ xp, int n)
{
    int j = blockIdx.x * blockDim.x + threadIdx.x;
    int total = n * 16, stride = gridDim.x * blockDim.x;
    for (int i = j; i < total; i += stride) {
        int row = i >> 4, wp = i & 15;
        float2 v = *(const float2*)(x + (size_t)row * 32 + wp * 2);
        unsigned short h0 = bf16u(v.x), h1 = bf16u(v.y);
        float l0 = v.x - __bfloat162float(__ushort_as_bfloat16(h0));
        float l1 = v.y - __bfloat162float(__ushort_as_bfloat16(h1));
        xp[(size_t)row * 32 + wp]      = (uint32_t)h0 | ((uint32_t)h1 << 16);
        xp[(size_t)row * 32 + 16 + wp] = (uint32_t)bf16u(l0) | ((uint32_t)bf16u(l1) << 16);
    }
}

__global__ void bnreluprep(const float* __restrict__ x, uint32_t* __restrict__ xp, int n)
{
    int j = blockIdx.x * blockDim.x + threadIdx.x;
    int total = n * 16, stride = gridDim.x * blockDim.x;
    int wp0 = j & 15;
    float sc0 = g_bn[2 * wp0], sc1 = g_bn[2 * wp0 + 1];
    float sh0 = g_bn[32 + 2 * wp0], sh1 = g_bn[33 + 2 * wp0];
    for (int i = j; i < total; i += stride) {
        int row = i >> 4, wp = i & 15;
        float2 v = *(const float2*)(x + (size_t)row * 32 + wp * 2);
        float a = fmaxf(v.x * sc0 + sh0, 0.f);
        float b = fmaxf(v.y * sc1 + sh1, 0.f);
        unsigned short h0 = bf16u(a), h1 = bf16u(b);
        float l0 = a - __bfloat162float(__ushort_as_bfloat16(h0));
        float l1 = b - __bfloat162float(__ushort_as_bfloat16(h1));
        xp[(size_t)row * 32 + wp]      = (uint32_t)h0 | ((uint32_t)h1 << 16);
        xp[(size_t)row * 32 + 16 + wp] = (uint32_t)bf16u(l0) | ((uint32_t)bf16u(l1) << 16);
    }
}

__global__ void reduce_kernel(const float* __restrict__ gamma,
                              const float* __restrict__ beta, int n, int nblk)
{
    __shared__ double sd[512];
    __shared__ double comb[64];
    const int t = threadIdx.x;
    const int c = t & 63, s = t >> 6;
    double acc = 0.0;
    for (int i = s; i < nblk; i += 8) acc += (double)g_part[(size_t)i * 64 + c];
    sd[t] = acc;
    __syncthreads();
    if (t < 64) {
        double a = 0.0;
        #pragma unroll
        for (int s2 = 0; s2 < 8; s2++) a += sd[t + 64 * s2];
        comb[t] = a;
    }
    __syncthreads();
    if (t < 32) {
        double mean = comb[t] / (double)n;
        double var  = comb[32 + t] / (double)n - mean * mean;
        float sc = (float)((double)gamma[t] / sqrt(var + 1e-4));
        float sh = (float)((double)beta[t] - mean * (double)sc);
        g_bn[t] = sc; g_bn[32 + t] = sh;
    }
}

__global__ void final_kernel(float* __restrict__ out, const float* __restrict__ feat, int n)
{
    int j = blockIdx.x * blockDim.x + threadIdx.x;
    int total = n * 8, stride = gridDim.x * blockDim.x;
    int m = j & 7;
    float4 sc = *(const float4*)(g_bn + m * 4);
    float4 sh = *(const float4*)(g_bn + 32 + m * 4);
    float4* o4 = (float4*)out;
    const float4* f4 = (const float4*)feat;
    for (int i = j; i < total; i += stride) {
        float4 v = o4[i], f = f4[i];
        v.x = fmaxf(v.x * sc.x + sh.x + f.x, 0.f);
        v.y = fmaxf(v.y * sc.y + sh.y + f.y, 0.f);
        v.z = fmaxf(v.z * sc.z + sh.z + f.z, 0.f);
        v.w = fmaxf(v.w * sc.w + sh.w + f.w, 0.f);
        o4[i] = v;
    }
}

extern "C" void kernel_launch(void* const* d_in, const int* in_sizes, int n_in,
                              void* d_out, int out_size)
{
    const float* feat = (const float*)d_in[0];
    const int*   nbr  = (const int*)  d_in[1];
    const float* W1   = (const float*)d_in[2];
    const float* g1   = (const float*)d_in[3];
    const float* b1   = (const float*)d_in[4];
    const float* W2   = (const float*)d_in[5];
    const float* g2   = (const float*)d_in[6];
    const float* b2   = (const float*)d_in[7];
    int n = in_sizes[0] / CH;
    float* out = (float*)d_out;

    float *h1, *xpf, *h1pf;
    uint32_t *w1i, *w2i;
    cudaGetSymbolAddress((void**)&h1,   g_h1);
    cudaGetSymbolAddress((void**)&xpf,  g_xp);
    cudaGetSymbolAddress((void**)&h1pf, g_h1p);
    cudaGetSymbolAddress((void**)&w1i,  g_w1img);
    cudaGetSymbolAddress((void**)&w2i,  g_w2img);

    cudaFuncSetAttribute(conv_mma, cudaFuncAttributeMaxDynamicSharedMemorySize, SM_TOT);
    int grid = (n + TM - 1) / TM;

    wprep<<<(KNB * 1024 + 255) / 256, 256>>>(W1, w1i);
    wprep<<<(KNB * 1024 + 255) / 256, 256>>>(W2, w2i);
    xprep<<<2048, 256>>>(feat, (uint32_t*)xpf, n);
    conv_mma<<<grid, 128, SM_TOT>>>((const uint32_t*)xpf, nbr, w1i, h1, n);
    reduce_kernel<<<1, 512>>>(g1, b1, n, grid);
    bnreluprep<<<2048, 256>>>(h1, (uint32_t*)h1pf, n);
    conv_mma<<<grid, 128, SM_TOT>>>((const uint32_t*)h1pf, nbr, w2i, out, n);
    reduce_kernel<<<1, 512>>>(g2, b2, n, grid);
    final_kernel<<<2048, 256>>>(out, feat, n);
}